// round 4
// baseline (speedup 1.0000x reference)
#include <cuda_runtime.h>
#include <cstdint>

// CRF forward scan, B blocks x 128 threads. Thread pair (2j,2j+1) owns state j:
// half h = tid&1 reduces i in [32h, 32h+32), combined via shfl_xor(1).
// alpha[j] <- feat[t,j] + c_j + m + log( sum_i exp(alpha[i]-m) * W[i][j] )
// W[i][j] = exp(trans[i][j]-c_j), c_j = max_i trans[i][j].
// m is a stale-by-2 block max (LSE shift-invariant).
// feats/masks staged CHUNK steps at a time into smem via cp.async (3-buf).

#define TT 64
#define CHUNK 16
typedef unsigned long long u64;

__device__ float g_Wt[TT * TT];  // g_Wt[j*64+i] = exp(trans[i][j]-c_j)
__device__ float g_c[TT];

__device__ __forceinline__ u64 pack2(float lo, float hi) {
    u64 r; asm("mov.b64 %0, {%1, %2};" : "=l"(r) : "f"(lo), "f"(hi)); return r;
}
__device__ __forceinline__ void unpack2(u64 v, float& lo, float& hi) {
    asm("mov.b64 {%0, %1}, %2;" : "=f"(lo), "=f"(hi) : "l"(v));
}
__device__ __forceinline__ u64 ffma2(u64 a, u64 b, u64 c) {
    u64 d; asm("fma.rn.f32x2 %0, %1, %2, %3;" : "=l"(d) : "l"(a), "l"(b), "l"(c)); return d;
}
__device__ __forceinline__ u64 fadd2(u64 a, u64 b) {
    u64 d; asm("add.rn.f32x2 %0, %1, %2;" : "=l"(d) : "l"(a), "l"(b)); return d;
}
__device__ __forceinline__ uint32_t smem_u32(const void* p) {
    uint32_t a;
    asm("{ .reg .u64 t; cvta.to.shared.u64 t, %1; cvt.u32.u64 %0, t; }" : "=r"(a) : "l"(p));
    return a;
}

// ---------------------------------------------------------------------------
__global__ void crf_prep_kernel(const float* __restrict__ trans) {
    int j = threadIdx.x;
    float c = -3.402823466e+38f;
    #pragma unroll
    for (int i = 0; i < TT; i++) c = fmaxf(c, trans[i * TT + j]);
    g_c[j] = c;
    #pragma unroll
    for (int i = 0; i < TT; i++) g_Wt[j * TT + i] = __expf(trans[i * TT + j] - c);
}

// ---------------------------------------------------------------------------
__global__ void __launch_bounds__(128) crf_scan_kernel(
    const float* __restrict__ feats,   // [B, S, 64]
    const float* __restrict__ masks,   // [B, S]
    float* __restrict__ out,           // [B, 64]
    int Sdim)
{
    const int b    = blockIdx.x;
    const int tid  = threadIdx.x;
    const int j    = tid >> 1;          // state (column) 0..63
    const int h    = tid & 1;           // half of the i-reduction
    const int warp = tid >> 5;
    const int lane = tid & 31;

    __shared__ float s_feat[3][CHUNK][TT];   // 12 KB staged feats
    __shared__ float s_mask[3][CHUNK];
    __shared__ float s_v[2][TT];             // exp(alpha - m), double buffered
    __shared__ float s_wm[4][4];             // per-warp maxima ring (4 warps)

    // Half of W column j: i in [32h, 32h+32) -> 16 packed f32x2 regs.
    u64 w[16];
    {
        const float4* wp = reinterpret_cast<const float4*>(&g_Wt[j * TT + 32 * h]);
        #pragma unroll
        for (int q = 0; q < 8; q++) {
            float4 f = wp[q];
            w[2 * q]     = pack2(f.x, f.y);
            w[2 * q + 1] = pack2(f.z, f.w);
        }
    }
    const float cj = g_c[j];

    const float* fbp = feats + (size_t)b * Sdim * TT;
    const float* mbp = masks + (size_t)b * Sdim;
    const uint32_t feat_s0 = smem_u32(&s_feat[0][0][0]);

    const int NC = (Sdim + CHUNK - 1) / CHUNK;

    // ---- stage chunk c into buffer c%3 (feats via cp.async, masks via LDG/STS)
    auto stage = [&](int c) {
        const int base = c * CHUNK;
        const int bufo = (c % 3) * CHUNK * TT;
        #pragma unroll
        for (int q = 0; q < 2; q++) {
            int g   = q * 128 + tid;       // 16B granule id, 0..255
            int row = g >> 4;
            int col = (g & 15) << 2;
            int gr  = base + row; if (gr >= Sdim) gr = Sdim - 1;
            const float* src = fbp + (size_t)gr * TT + col;
            uint32_t dst = feat_s0 + (uint32_t)(bufo + row * TT + col) * 4u;
            asm volatile("cp.async.cg.shared.global [%0], [%1], 16;" :: "r"(dst), "l"(src));
        }
        if (tid < CHUNK) {
            int gr = base + tid; if (gr >= Sdim) gr = Sdim - 1;
            s_mask[c % 3][tid] = mbp[gr];
        }
    };

    // Prologue: chunks 0 and 1 in flight; chunk 0 resident before alpha init.
    stage(0);
    asm volatile("cp.async.commit_group;");
    if (NC > 1) stage(1);
    asm volatile("cp.async.commit_group;");
    asm volatile("cp.async.wait_group 1;");
    __syncthreads();

    float alpha = s_feat[0][0][j];           // alpha0 (both lanes of pair carry it)

    // Exact initial shift + seed the wm ring for step 1's read.
    {
        float wmx = alpha;
        #pragma unroll
        for (int o = 16; o > 0; o >>= 1)
            wmx = fmaxf(wmx, __shfl_xor_sync(0xffffffffu, wmx, o));
        if (lane == 0) s_wm[1][warp] = wmx;
    }
    __syncthreads();
    float m = fmaxf(fmaxf(s_wm[1][0], s_wm[1][1]), fmaxf(s_wm[1][2], s_wm[1][3]));

    for (int c = 0; c < NC; c++) {
        if (c > 0) asm volatile("cp.async.wait_group 1;");  // chunk c resident
        if (c + 2 < NC) stage(c + 2);
        asm volatile("cp.async.commit_group;");             // uniform group count
        __syncthreads();

        #pragma unroll
        for (int r = 0; r < CHUNK; r++) {
            const int t = c * CHUNK + r;
            if (t >= 1 && t < Sdim) {                       // uniform guard
                // exp with stale shift; even lane of pair publishes v[j]
                const float v = __expf(alpha - m);
                if (h == 0) s_v[r & 1][j] = v;
                __syncthreads();

                // half matvec: sum over i in [32h, 32h+32)
                const float4* vp =
                    reinterpret_cast<const float4*>(&s_v[r & 1][32 * h]);
                u64 acc[4] = {0ull, 0ull, 0ull, 0ull};
                #pragma unroll
                for (int q = 0; q < 8; q++) {
                    float4 f = vp[q];
                    acc[(2 * q) & 3]     = ffma2(pack2(f.x, f.y), w[2 * q],     acc[(2 * q) & 3]);
                    acc[(2 * q + 1) & 3] = ffma2(pack2(f.z, f.w), w[2 * q + 1], acc[(2 * q + 1) & 3]);
                }
                u64 s2 = fadd2(fadd2(acc[0], acc[1]), fadd2(acc[2], acc[3]));
                float lo, hi; unpack2(s2, lo, hi);
                float P = lo + hi;
                // combine the two halves of column j (pair = adjacent lanes)
                P += __shfl_xor_sync(0xffffffffu, P, 1);

                // shift for step t+2: warp-max of current alpha (overlaps matvec)
                const float mnext =
                    fmaxf(fmaxf(s_wm[r & 3][0], s_wm[r & 3][1]),
                          fmaxf(s_wm[r & 3][2], s_wm[r & 3][3]));
                float wmx = alpha;
                #pragma unroll
                for (int o = 16; o > 0; o >>= 1)
                    wmx = fmaxf(wmx, __shfl_xor_sync(0xffffffffu, wmx, o));
                if (lane == 0) s_wm[(r + 1) & 3][warp] = wmx;

                const float ft = s_feat[c % 3][r][j];
                const float mk = s_mask[c % 3][r];
                const float na = ft + cj + m + __logf(P);
                alpha = na * mk + alpha * (1.0f - mk);
                m = mnext;
            }
        }
    }

    if (h == 0) out[(size_t)b * TT + j] = alpha;
}

// ---------------------------------------------------------------------------
extern "C" void kernel_launch(void* const* d_in, const int* in_sizes, int n_in,
                              void* d_out, int out_size) {
    const float* feats = (const float*)d_in[0];
    const float* masks = (const float*)d_in[1];
    const float* trans = (const float*)d_in[2];
    float* out = (float*)d_out;

    const int Bn   = out_size / TT;
    const int Sdim = in_sizes[0] / (Bn * TT);

    crf_prep_kernel<<<1, TT>>>(trans);
    crf_scan_kernel<<<Bn, 128>>>(feats, masks, out, Sdim);
}

// round 5
// speedup vs baseline: 1.3292x; 1.3292x over previous
#include <cuda_runtime.h>
#include <cstdint>

// CRF forward scan — ONE WARP PER BATCH, zero block barriers.
// Thread `lane` owns states jA=lane, jB=lane+32 (full 64-MAC columns each).
// alpha[j] <- feat[t,j] + c_j + m + log( sum_i exp(alpha[i]-m) * W[i][j] )
// W[i][j] = exp(trans[i][j]-c_j), c_j = max_i trans[i][j].
// m = warp max of alpha, stale by 1 step (LSE shift-invariant; drift tiny).
// feats+masks staged CHUNK steps ahead via per-warp cp.async 3-buffer pipeline.
// 2 independent warps per block (grid = B/2) so 256 blocks cover all 148 SMs.

#define TT 64
#define CHUNK 16
typedef unsigned long long u64;

__device__ float g_Wt[TT * TT];  // g_Wt[j*64+i] = exp(trans[i][j]-c_j)
__device__ float g_c[TT];

__device__ __forceinline__ u64 pack2(float lo, float hi) {
    u64 r; asm("mov.b64 %0, {%1, %2};" : "=l"(r) : "f"(lo), "f"(hi)); return r;
}
__device__ __forceinline__ void unpack2(u64 v, float& lo, float& hi) {
    asm("mov.b64 {%0, %1}, %2;" : "=f"(lo), "=f"(hi) : "l"(v));
}
__device__ __forceinline__ u64 ffma2(u64 a, u64 b, u64 c) {
    u64 d; asm("fma.rn.f32x2 %0, %1, %2, %3;" : "=l"(d) : "l"(a), "l"(b), "l"(c)); return d;
}
__device__ __forceinline__ u64 fadd2(u64 a, u64 b) {
    u64 d; asm("add.rn.f32x2 %0, %1, %2;" : "=l"(d) : "l"(a), "l"(b)); return d;
}
__device__ __forceinline__ uint32_t smem_u32(const void* p) {
    uint32_t a;
    asm("{ .reg .u64 t; cvta.to.shared.u64 t, %1; cvt.u32.u64 %0, t; }" : "=r"(a) : "l"(p));
    return a;
}

// ---------------------------------------------------------------------------
__global__ void crf_prep_kernel(const float* __restrict__ trans) {
    int j = threadIdx.x;
    float c = -3.402823466e+38f;
    #pragma unroll
    for (int i = 0; i < TT; i++) c = fmaxf(c, trans[i * TT + j]);
    g_c[j] = c;
    #pragma unroll
    for (int i = 0; i < TT; i++) g_Wt[j * TT + i] = __expf(trans[i * TT + j] - c);
}

// ---------------------------------------------------------------------------
__global__ void __launch_bounds__(64) crf_scan_kernel(
    const float* __restrict__ feats,   // [B, S, 64]
    const float* __restrict__ masks,   // [B, S]
    float* __restrict__ out,           // [B, 64]
    int Sdim, int Bn)
{
    const int warp = threadIdx.x >> 5;
    const int lane = threadIdx.x & 31;
    const int b    = blockIdx.x * 2 + warp;
    if (b >= Bn) return;                       // warps fully independent

    const int jA = lane;
    const int jB = lane + 32;

    // Per-warp private shared regions — no cross-warp sharing anywhere.
    __shared__ float s_feat[2][3][CHUNK][TT];  // 24 KB
    __shared__ float s_mask[2][3][CHUNK];
    __shared__ float s_v[2][2][TT];

    // Full W columns jA, jB in packed f32x2 registers.
    u64 wA[32], wB[32];
    {
        const float4* pa = reinterpret_cast<const float4*>(&g_Wt[jA * TT]);
        const float4* pb = reinterpret_cast<const float4*>(&g_Wt[jB * TT]);
        #pragma unroll
        for (int q = 0; q < 16; q++) {
            float4 fa = pa[q];
            wA[2 * q]     = pack2(fa.x, fa.y);
            wA[2 * q + 1] = pack2(fa.z, fa.w);
            float4 fq = pb[q];
            wB[2 * q]     = pack2(fq.x, fq.y);
            wB[2 * q + 1] = pack2(fq.z, fq.w);
        }
    }
    const float cA = g_c[jA];
    const float cB = g_c[jB];

    const float* fbp = feats + (size_t)b * Sdim * TT;
    const float* mbp = masks + (size_t)b * Sdim;
    const uint32_t feat_s0 = smem_u32(&s_feat[warp][0][0][0]);
    const uint32_t mask_s0 = smem_u32(&s_mask[warp][0][0]);

    const int NC = (Sdim + CHUNK - 1) / CHUNK;

    // Stage chunk c into buffer c%3. All async: 8x16B feats + 16x4B masks.
    auto stage = [&](int c) {
        const int base = c * CHUNK;
        const int bufo = (c % 3) * CHUNK * TT;
        #pragma unroll
        for (int q = 0; q < 8; q++) {
            int g   = q * 32 + lane;           // granule 0..255 (16B each)
            int row = g >> 4;                  // 16 granules per 64-float row
            int col = (g & 15) << 2;
            int gr  = base + row; if (gr >= Sdim) gr = Sdim - 1;
            const float* src = fbp + (size_t)gr * TT + col;
            uint32_t dst = feat_s0 + (uint32_t)(bufo + row * TT + col) * 4u;
            asm volatile("cp.async.cg.shared.global [%0], [%1], 16;" :: "r"(dst), "l"(src));
        }
        if (lane < CHUNK) {
            int gr = base + lane; if (gr >= Sdim) gr = Sdim - 1;
            const float* src = mbp + gr;
            uint32_t dst = mask_s0 + (uint32_t)((c % 3) * CHUNK + lane) * 4u;
            asm volatile("cp.async.ca.shared.global [%0], [%1], 4;" :: "r"(dst), "l"(src));
        }
    };

    // Prologue: chunks 0,1 in flight; chunk 0 resident before alpha init.
    stage(0);
    asm volatile("cp.async.commit_group;");
    if (NC > 1) stage(1);
    asm volatile("cp.async.commit_group;");
    asm volatile("cp.async.wait_group 1;");
    __syncwarp();

    float aA = s_feat[warp][0][0][jA];         // alpha0
    float aB = s_feat[warp][0][0][jB];

    // Exact initial shift.
    float m = fmaxf(aA, aB);
    #pragma unroll
    for (int o = 16; o > 0; o >>= 1)
        m = fmaxf(m, __shfl_xor_sync(0xffffffffu, m, o));

    for (int c = 0; c < NC; c++) {
        if (c > 0) asm volatile("cp.async.wait_group 1;");
        if (c + 2 < NC) stage(c + 2);
        asm volatile("cp.async.commit_group;");            // uniform group count
        __syncwarp();

        #pragma unroll
        for (int r = 0; r < CHUNK; r++) {
            const int t = c * CHUNK + r;
            if (t >= 1 && t < Sdim) {
                // exp with stale-by-1 shift; publish both v values.
                const float vA = __expf(aA - m);
                const float vB = __expf(aB - m);
                s_v[warp][r & 1][jA] = vA;
                s_v[warp][r & 1][jB] = vB;

                // Next step's shift from CURRENT alpha (overlaps matvec).
                float mn = fmaxf(aA, aB);
                #pragma unroll
                for (int o = 16; o > 0; o >>= 1)
                    mn = fmaxf(mn, __shfl_xor_sync(0xffffffffu, mn, o));

                __syncwarp();

                // Matvec for both columns: P_j = sum_i v_i * W[i][j].
                const float4* vp = reinterpret_cast<const float4*>(s_v[warp][r & 1]);
                u64 accA[4] = {0ull, 0ull, 0ull, 0ull};
                u64 accB[4] = {0ull, 0ull, 0ull, 0ull};
                #pragma unroll
                for (int q = 0; q < 16; q++) {
                    float4 f = vp[q];                      // broadcast ld.shared.v4
                    u64 v01 = pack2(f.x, f.y);
                    u64 v23 = pack2(f.z, f.w);
                    accA[(2 * q) & 3]     = ffma2(v01, wA[2 * q],     accA[(2 * q) & 3]);
                    accA[(2 * q + 1) & 3] = ffma2(v23, wA[2 * q + 1], accA[(2 * q + 1) & 3]);
                    accB[(2 * q) & 3]     = ffma2(v01, wB[2 * q],     accB[(2 * q) & 3]);
                    accB[(2 * q + 1) & 3] = ffma2(v23, wB[2 * q + 1], accB[(2 * q + 1) & 3]);
                }
                u64 sA = fadd2(fadd2(accA[0], accA[1]), fadd2(accA[2], accA[3]));
                u64 sB = fadd2(fadd2(accB[0], accB[1]), fadd2(accB[2], accB[3]));
                float al, ah, bl, bh;
                unpack2(sA, al, ah);
                unpack2(sB, bl, bh);
                const float PA = al + ah;
                const float PB = bl + bh;

                const float fA = s_feat[warp][c % 3][r][jA];
                const float fB = s_feat[warp][c % 3][r][jB];
                const float mk = s_mask[warp][c % 3][r];
                const float nA = fA + cA + m + __logf(PA);
                const float nB = fB + cB + m + __logf(PB);
                aA = nA * mk + aA * (1.0f - mk);
                aB = nB * mk + aB * (1.0f - mk);
                m = mn;
            }
        }
    }

    out[(size_t)b * TT + jA] = aA;
    out[(size_t)b * TT + jB] = aB;
}

// ---------------------------------------------------------------------------
extern "C" void kernel_launch(void* const* d_in, const int* in_sizes, int n_in,
                              void* d_out, int out_size) {
    const float* feats = (const float*)d_in[0];
    const float* masks = (const float*)d_in[1];
    const float* trans = (const float*)d_in[2];
    float* out = (float*)d_out;

    const int Bn   = out_size / TT;
    const int Sdim = in_sizes[0] / (Bn * TT);

    crf_prep_kernel<<<1, TT>>>(trans);
    crf_scan_kernel<<<(Bn + 1) / 2, 64>>>(feats, masks, out, Sdim, Bn);
}

// round 6
// speedup vs baseline: 1.8534x; 1.3943x over previous
#include <cuda_runtime.h>
#include <cstdint>

// CRF forward scan, B blocks x 64 threads (thread j = state j; warp = j>>5).
// alpha[j] <- feat[t,j] + c_j + m + log( sum_i exp(alpha[i]-m) * W[i][j] )
// W[i][j] = exp(trans[i][j]-c_j), c_j = max_i trans[i][j].
// m is a stale-by-2 block max (LSE shift-invariant).
// Split matvec: own warp's v-half consumed after __syncwarp (pre-barrier),
// other warp's half after the single per-step __syncthreads.
// feats+masks staged CHUNK steps ahead via cp.async 3-buffer pipeline.

#define TT 64
#define CHUNK 16
typedef unsigned long long u64;

__device__ float g_Wt[TT * TT];  // g_Wt[j*64+i] = exp(trans[i][j]-c_j)
__device__ float g_c[TT];

__device__ __forceinline__ u64 pack2(float lo, float hi) {
    u64 r; asm("mov.b64 %0, {%1, %2};" : "=l"(r) : "f"(lo), "f"(hi)); return r;
}
__device__ __forceinline__ void unpack2(u64 v, float& lo, float& hi) {
    asm("mov.b64 {%0, %1}, %2;" : "=f"(lo), "=f"(hi) : "l"(v));
}
__device__ __forceinline__ u64 ffma2(u64 a, u64 b, u64 c) {
    u64 d; asm("fma.rn.f32x2 %0, %1, %2, %3;" : "=l"(d) : "l"(a), "l"(b), "l"(c)); return d;
}
__device__ __forceinline__ u64 fadd2(u64 a, u64 b) {
    u64 d; asm("add.rn.f32x2 %0, %1, %2;" : "=l"(d) : "l"(a), "l"(b)); return d;
}
__device__ __forceinline__ uint32_t smem_u32(const void* p) {
    uint32_t a;
    asm("{ .reg .u64 t; cvta.to.shared.u64 t, %1; cvt.u32.u64 %0, t; }" : "=r"(a) : "l"(p));
    return a;
}

// ---------------------------------------------------------------------------
__global__ void crf_prep_kernel(const float* __restrict__ trans) {
    int j = threadIdx.x;
    float c = -3.402823466e+38f;
    #pragma unroll
    for (int i = 0; i < TT; i++) c = fmaxf(c, trans[i * TT + j]);
    g_c[j] = c;
    #pragma unroll
    for (int i = 0; i < TT; i++) g_Wt[j * TT + i] = __expf(trans[i * TT + j] - c);
}

// ---------------------------------------------------------------------------
__global__ void __launch_bounds__(64) crf_scan_kernel(
    const float* __restrict__ feats,   // [B, S, 64]
    const float* __restrict__ masks,   // [B, S]
    float* __restrict__ out,           // [B, 64]
    int Sdim)
{
    const int b    = blockIdx.x;
    const int j    = threadIdx.x;
    const int warp = j >> 5;
    const int lane = j & 31;

    __shared__ float s_feat[3][CHUNK][TT];   // 12 KB staged feats
    __shared__ float s_mask[3][CHUNK];
    __shared__ float s_v[2][TT];             // exp(alpha - m), double buffered
    __shared__ float s_wm[4][2];             // per-warp maxima ring

    // W column j, split: wlo = rows [32*warp, 32*warp+32) (own warp's half),
    // whi = the other 32 rows. Constant register indices — no spills.
    u64 wlo[16], whi[16];
    {
        const float4* plo = reinterpret_cast<const float4*>(&g_Wt[j * TT + 32 * warp]);
        const float4* phi = reinterpret_cast<const float4*>(&g_Wt[j * TT + 32 * (warp ^ 1)]);
        #pragma unroll
        for (int q = 0; q < 8; q++) {
            float4 fl = plo[q];
            wlo[2 * q]     = pack2(fl.x, fl.y);
            wlo[2 * q + 1] = pack2(fl.z, fl.w);
            float4 fh = phi[q];
            whi[2 * q]     = pack2(fh.x, fh.y);
            whi[2 * q + 1] = pack2(fh.z, fh.w);
        }
    }
    const float cj = g_c[j];

    const float* fbp = feats + (size_t)b * Sdim * TT;
    const float* mbp = masks + (size_t)b * Sdim;
    const uint32_t feat_s0 = smem_u32(&s_feat[0][0][0]);
    const uint32_t mask_s0 = smem_u32(&s_mask[0][0]);

    const int NC = (Sdim + CHUNK - 1) / CHUNK;

    // Stage chunk c into buffer c%3 — fully async (no LDG stalls).
    auto stage = [&](int c) {
        const int base = c * CHUNK;
        const int bufo = (c % 3) * CHUNK * TT;
        #pragma unroll
        for (int q = 0; q < 4; q++) {
            int g   = q * 64 + j;          // 16B granule id, 0..255
            int row = g >> 4;
            int col = (g & 15) << 2;
            int gr  = base + row; if (gr >= Sdim) gr = Sdim - 1;
            const float* src = fbp + (size_t)gr * TT + col;
            uint32_t dst = feat_s0 + (uint32_t)(bufo + row * TT + col) * 4u;
            asm volatile("cp.async.cg.shared.global [%0], [%1], 16;" :: "r"(dst), "l"(src));
        }
        if (j < CHUNK) {
            int gr = base + j; if (gr >= Sdim) gr = Sdim - 1;
            const float* src = mbp + gr;
            uint32_t dst = mask_s0 + (uint32_t)((c % 3) * CHUNK + j) * 4u;
            asm volatile("cp.async.ca.shared.global [%0], [%1], 4;" :: "r"(dst), "l"(src));
        }
    };

    // Prologue: chunks 0,1 in flight; chunk 0 resident before alpha init.
    stage(0);
    asm volatile("cp.async.commit_group;");
    if (NC > 1) stage(1);
    asm volatile("cp.async.commit_group;");
    asm volatile("cp.async.wait_group 1;");
    __syncthreads();

    float alpha = s_feat[0][0][j];           // alpha0 = feats[b,0,:]

    // Exact initial shift + seed the wm ring for step 1's read.
    {
        float wmx = alpha;
        #pragma unroll
        for (int o = 16; o > 0; o >>= 1)
            wmx = fmaxf(wmx, __shfl_xor_sync(0xffffffffu, wmx, o));
        if (lane == 0) s_wm[1][warp] = wmx;
    }
    __syncthreads();
    float m = fmaxf(s_wm[1][0], s_wm[1][1]);

    for (int c = 0; c < NC; c++) {
        if (c > 0) asm volatile("cp.async.wait_group 1;");  // chunk c resident
        if (c + 2 < NC) stage(c + 2);
        asm volatile("cp.async.commit_group;");             // uniform group count
        __syncthreads();

        #pragma unroll
        for (int r = 0; r < CHUNK; r++) {
            const int t = c * CHUNK + r;
            if (t >= 1 && t < Sdim) {                       // uniform guard
                // exp with stale shift; publish v[j]
                const float v = __expf(alpha - m);
                s_v[r & 1][j] = v;
                __syncwarp();

                // ---- own-half matvec: i in [32*warp, 32*warp+32) ----
                const float4* vlo =
                    reinterpret_cast<const float4*>(&s_v[r & 1][32 * warp]);
                u64 acc[4] = {0ull, 0ull, 0ull, 0ull};
                #pragma unroll
                for (int q = 0; q < 8; q++) {
                    float4 f = vlo[q];
                    acc[(2 * q) & 3]     = ffma2(pack2(f.x, f.y), wlo[2 * q],     acc[(2 * q) & 3]);
                    acc[(2 * q + 1) & 3] = ffma2(pack2(f.z, f.w), wlo[2 * q + 1], acc[(2 * q + 1) & 3]);
                }

                // Off-chain work while waiting: feat/mask + stale-max tree.
                const float ft = s_feat[c % 3][r][j];
                const float mk = s_mask[c % 3][r];
                const float mnext = fmaxf(s_wm[r & 3][0], s_wm[r & 3][1]);
                float wmx = alpha;
                #pragma unroll
                for (int o = 16; o > 0; o >>= 1)
                    wmx = fmaxf(wmx, __shfl_xor_sync(0xffffffffu, wmx, o));
                if (lane == 0) s_wm[(r + 1) & 3][warp] = wmx;

                __syncthreads();   // other warp's v-half now visible

                // ---- other-half matvec: i in [32*(warp^1), +32) ----
                const float4* vhi =
                    reinterpret_cast<const float4*>(&s_v[r & 1][32 * (warp ^ 1)]);
                #pragma unroll
                for (int q = 0; q < 8; q++) {
                    float4 f = vhi[q];
                    acc[(2 * q) & 3]     = ffma2(pack2(f.x, f.y), whi[2 * q],     acc[(2 * q) & 3]);
                    acc[(2 * q + 1) & 3] = ffma2(pack2(f.z, f.w), whi[2 * q + 1], acc[(2 * q + 1) & 3]);
                }
                u64 s2 = fadd2(fadd2(acc[0], acc[1]), fadd2(acc[2], acc[3]));
                float lo, hi; unpack2(s2, lo, hi);
                const float P = lo + hi;

                const float na = ft + cj + m + __logf(P);
                alpha = na * mk + alpha * (1.0f - mk);
                m = mnext;
            }
        }
    }

    out[(size_t)b * TT + j] = alpha;
}

// ---------------------------------------------------------------------------
extern "C" void kernel_launch(void* const* d_in, const int* in_sizes, int n_in,
                              void* d_out, int out_size) {
    const float* feats = (const float*)d_in[0];
    const float* masks = (const float*)d_in[1];
    const float* trans = (const float*)d_in[2];
    float* out = (float*)d_out;

    const int Bn   = out_size / TT;
    const int Sdim = in_sizes[0] / (Bn * TT);

    crf_prep_kernel<<<1, TT>>>(trans);
    crf_scan_kernel<<<Bn, TT>>>(feats, masks, out, Sdim);
}